// round 16
// baseline (speedup 1.0000x reference)
#include <cuda_runtime.h>
#include <cuda_bf16.h>
#include <math.h>
#include <stdint.h>

#define TT   128
#define BB   512
#define DD   512
#define MM   6
#define JJ   (TT + MM)
#define HH   2
#define DFF  64
#define ACT  64
#define NROW (TT * BB)
#define MROW (MM * BB)
#define BG   0.1f

typedef __nv_bfloat16 bf16;

// ---------- static scratch ----------
__device__ __align__(256) float g_qkv[NROW * 192];
__device__ __align__(256) float g_kvm[MROW * 128];
__device__ __align__(256) float g_p  [JJ * 64];
__device__ __align__(256) float g_ts [BB * DD];
__device__ __align__(256) float g_h1 [BB * 1024];
__device__ __align__(256) float g_h2 [BB * 512];
__device__ __align__(256) float g_h3 [BB * 300];
__device__ __align__(256) float g_bc2[3 * DD];
__device__ __align__(256) float g_cg [256];
__device__ __align__(256) float g_cbb[256];
__device__ __align__(256) float2 g_st1[NROW];
__device__ __align__(256) float2 g_st2[NROW];
__device__ __align__(256) bf16 gb_x   [NROW * DD];
__device__ __align__(256) bf16 gb_mem [MROW * DD];
__device__ __align__(256) bf16 gb_rx  [NROW * DD];
__device__ __align__(256) bf16 gb_z   [NROW * DD];
__device__ __align__(256) bf16 gb_src [NROW * DD];
__device__ __align__(256) bf16 gb_ffh [NROW * DFF];
__device__ __align__(256) bf16 gb_av  [NROW * 64];
__device__ __align__(256) bf16 gb_wqkv[192 * DD];   // LN1-g-scaled [Wq|Wkv]^T
__device__ __align__(256) bf16 gb_wkvm[128 * DD];   // raw Wkv^T (memory rows)
__device__ __align__(256) bf16 gb_g1  [6 * DD * DD];
__device__ __align__(256) bf16 gb_g2  [6 * DD * DD];
__device__ __align__(256) bf16 gb_ff1 [DFF * DD];   // LN2-g-scaled ff_W1^T
__device__ __align__(256) bf16 gb_cw  [6 * DD * 64];

// ---------- helpers ----------
__device__ __forceinline__ uint32_t s2u(const void* p) {
    return (uint32_t)__cvta_generic_to_shared(p);
}
__device__ __forceinline__ void cp16(uint32_t s, const void* g) {
    asm volatile("cp.async.cg.shared.global [%0], [%1], 16;" :: "r"(s), "l"(g));
}
__device__ __forceinline__ void cp_commit() { asm volatile("cp.async.commit_group;" ::: "memory"); }
__device__ __forceinline__ void cp_wait0()  { asm volatile("cp.async.wait_group 0;" ::: "memory"); }
__device__ __forceinline__ void cp_wait1()  { asm volatile("cp.async.wait_group 1;" ::: "memory"); }
__device__ __forceinline__ void ldsm4(uint32_t* r, uint32_t addr) {
    asm volatile("ldmatrix.sync.aligned.m8n8.x4.shared.b16 {%0,%1,%2,%3}, [%4];"
                 : "=r"(r[0]), "=r"(r[1]), "=r"(r[2]), "=r"(r[3]) : "r"(addr));
}
__device__ __forceinline__ void mma_bf16(float* c, const uint32_t* a, const uint32_t* b) {
    asm volatile(
        "mma.sync.aligned.m16n8k16.row.col.f32.bf16.bf16.f32 "
        "{%0,%1,%2,%3}, {%4,%5,%6,%7}, {%8,%9}, {%0,%1,%2,%3};"
        : "+f"(c[0]), "+f"(c[1]), "+f"(c[2]), "+f"(c[3])
        : "r"(a[0]), "r"(a[1]), "r"(a[2]), "r"(a[3]), "r"(b[0]), "r"(b[1]));
}
__device__ __forceinline__ float tanh_fast(float x) {
    float r;
    asm("tanh.approx.f32 %0, %1;" : "=f"(r) : "f"(x));
    return r;
}
__device__ __forceinline__ float sig_fast(float x) {
    return fmaf(0.5f, tanh_fast(0.5f * x), 0.5f);
}

// ---------- bf16 dual-source tensor GEMM ----------
// modes: 0 f32 | 2 bf16 | 3 bf16 relu | 4 bf16 = sigmoid(v)*aux
//        5 gate combine | 6 f32 LN-fold (rstat,cg,cbb) | 7 bf16 relu LN-fold

template<int NT>
__global__ __launch_bounds__(256, 2)
void bgemm(const bf16* __restrict__ A0, const bf16* __restrict__ W0, int K0,
           const bf16* __restrict__ A1, const bf16* __restrict__ W1, int K1,
           int N,
           float* __restrict__ Cf, bf16* __restrict__ Cb,
           const float* __restrict__ bias1, const float* __restrict__ bias2,
           float cadd, const bf16* __restrict__ zpre, const bf16* __restrict__ aux,
           const float2* __restrict__ rstat, int mode)
{
    extern __shared__ char dsm[];
    constexpr int NTI = NT / 32;
    constexpr int STG = (128 + NT) * 144;

    const int tid  = threadIdx.x;
    const int warp = tid >> 5, lane = tid & 31;
    const int grp  = lane >> 2, thr = lane & 3;
    const int wm   = warp & 1,  wn  = warp >> 1;
    const int m_base = wm * 64;
    const int n_base = wn * (NT / 4);
    const int row0 = blockIdx.y * 128;
    const int col0 = blockIdx.x * NT;
    const uint32_t sb = s2u(dsm);

    float acc[4][NTI][4];
#pragma unroll
    for (int i = 0; i < 4; i++)
#pragma unroll
        for (int j = 0; j < NTI; j++)
#pragma unroll
            for (int r = 0; r < 4; r++) acc[i][j][r] = 0.f;

    const int NC0 = K0 >> 6;
    const int NC  = NC0 + (K1 >> 6);

    auto load_stage = [&](int c, int buf) {
        const bf16 *a, *w; int k, kb;
        if (c < NC0) { a = A0; w = W0; k = K0; kb = c << 6; }
        else         { a = A1; w = W1; k = K1; kb = (c - NC0) << 6; }
        uint32_t ab = sb + (uint32_t)buf * STG;
#pragma unroll
        for (int i = 0; i < 4; i++) {
            int u = tid + i * 256;
            int r = u >> 3, cc = u & 7;
            cp16(ab + (uint32_t)(r * 144 + cc * 16),
                 a + (size_t)(row0 + r) * k + kb + cc * 8);
        }
        uint32_t bb = ab + 128u * 144u;
#pragma unroll
        for (int i = 0; i < NT / 32; i++) {
            int u = tid + i * 256;
            int r = u >> 3, cc = u & 7;
            cp16(bb + (uint32_t)(r * 144 + cc * 16),
                 w + (size_t)(col0 + r) * k + kb + cc * 8);
        }
        cp_commit();
    };

    load_stage(0, 0);
    if (NC > 1) load_stage(1, 1);

    for (int c = 0; c < NC; c++) {
        if (c == NC - 1) cp_wait0(); else cp_wait1();
        __syncthreads();
        if (c + 2 < NC) load_stage(c + 2, (c + 2) % 3);

        uint32_t ab = sb + (uint32_t)(c % 3) * STG;
        uint32_t bb = ab + 128u * 144u;

        const uint32_t a_lrow = (uint32_t)(lane & 15);
        const uint32_t a_koff = (uint32_t)((lane >> 4) << 3);
        const uint32_t b_cofs = (uint32_t)(((lane >> 4) << 3) + (lane & 7));
        const uint32_t b_koff = (uint32_t)(((lane >> 3) & 1) << 3);

#pragma unroll
        for (int ks = 0; ks < 4; ks++) {
            const int kc = ks * 16;
            uint32_t af[4][4], bfr[NTI][2];
#pragma unroll
            for (int mt = 0; mt < 4; mt++) {
                uint32_t addr = ab + (uint32_t)(m_base + mt * 16 + a_lrow) * 144u
                                   + (uint32_t)(kc + a_koff) * 2u;
                ldsm4(af[mt], addr);
            }
#pragma unroll
            for (int p = 0; p < NTI / 2; p++) {
                uint32_t col = (uint32_t)(n_base + p * 16) + b_cofs;
                uint32_t addr = bb + col * 144u + (uint32_t)(kc + b_koff) * 2u;
                uint32_t r[4];
                ldsm4(r, addr);
                bfr[2 * p][0]     = r[0]; bfr[2 * p][1]     = r[1];
                bfr[2 * p + 1][0] = r[2]; bfr[2 * p + 1][1] = r[3];
            }
#pragma unroll
            for (int mt = 0; mt < 4; mt++)
#pragma unroll
                for (int nt = 0; nt < NTI; nt++)
                    mma_bf16(acc[mt][nt], af[mt], bfr[nt]);
        }
    }

    // epilogue
#pragma unroll
    for (int mt = 0; mt < 4; mt++) {
#pragma unroll
        for (int nt = 0; nt < NTI; nt++) {
            int cbase = col0 + n_base + nt * 8 + thr * 2;
            if (mode >= 6) {
                float cg0 = bias1[cbase], cg1 = bias1[cbase + 1];
                float cb0 = bias2[cbase], cb1 = bias2[cbase + 1];
#pragma unroll
                for (int half = 0; half < 2; half++) {
                    int r = row0 + m_base + mt * 16 + grp + half * 8;
                    size_t idx = (size_t)r * N + cbase;
                    float2 st = rstat[r];
                    float off = -st.y * st.x;
                    float v0 = fmaf(st.y, acc[mt][nt][half * 2 + 0], fmaf(off, cg0, cb0));
                    float v1 = fmaf(st.y, acc[mt][nt][half * 2 + 1], fmaf(off, cg1, cb1));
                    if (mode == 6) {
                        *reinterpret_cast<float2*>(Cf + idx) = make_float2(v0, v1);
                    } else {
                        *reinterpret_cast<__nv_bfloat162*>(Cb + idx) =
                            __floats2bfloat162_rn(fmaxf(v0, 0.f), fmaxf(v1, 0.f));
                    }
                }
                continue;
            }
            float b0 = cadd, b1 = cadd;
            if (bias1) { b0 += bias1[cbase]; b1 += bias1[cbase + 1]; }
            if (bias2) { b0 += bias2[cbase]; b1 += bias2[cbase + 1]; }
#pragma unroll
            for (int half = 0; half < 2; half++) {
                int r = row0 + m_base + mt * 16 + grp + half * 8;
                size_t idx = (size_t)r * N + cbase;
                float v0 = acc[mt][nt][half * 2 + 0] + b0;
                float v1 = acc[mt][nt][half * 2 + 1] + b1;
                if (mode == 0) {
                    *reinterpret_cast<float2*>(Cf + idx) = make_float2(v0, v1);
                } else if (mode == 2) {
                    *reinterpret_cast<__nv_bfloat162*>(Cb + idx) = __floats2bfloat162_rn(v0, v1);
                } else if (mode == 3) {
                    *reinterpret_cast<__nv_bfloat162*>(Cb + idx) =
                        __floats2bfloat162_rn(fmaxf(v0, 0.f), fmaxf(v1, 0.f));
                } else if (mode == 4) {
                    __nv_bfloat162 a2 = *reinterpret_cast<const __nv_bfloat162*>(aux + idx);
                    *reinterpret_cast<__nv_bfloat162*>(Cb + idx) =
                        __floats2bfloat162_rn(sig_fast(v0) * __bfloat162float(a2.x),
                                              sig_fast(v1) * __bfloat162float(a2.y));
                } else {
                    __nv_bfloat162 z2 = *reinterpret_cast<const __nv_bfloat162*>(zpre + idx);
                    __nv_bfloat162 a2 = *reinterpret_cast<const __nv_bfloat162*>(aux + idx);
                    float z0 = sig_fast(__bfloat162float(z2.x));
                    float z1 = sig_fast(__bfloat162float(z2.y));
                    float o0 = (1.f - z0) * __bfloat162float(a2.x) + z0 * tanh_fast(v0);
                    float o1 = (1.f - z1) * __bfloat162float(a2.y) + z1 * tanh_fast(v1);
                    if (Cf) *reinterpret_cast<float2*>(Cf + idx) = make_float2(o0, o1);
                    if (Cb) *reinterpret_cast<__nv_bfloat162*>(Cb + idx) =
                        __floats2bfloat162_rn(o0, o1);
                }
            }
        }
    }
}

// ---------- exact fp32 GEMM, 64x64 tiles (critic head) ----------
__global__ void sgemm64_kernel(const float* __restrict__ A, const float* __restrict__ W,
                               float* __restrict__ C, int M, int N, int K,
                               const float* __restrict__ bias, float cadd, int flags)
{
    __shared__ float As[8][64];
    __shared__ float Bs[8][65];
    int tid = threadIdx.x;
    int row0 = blockIdx.y * 64, col0 = blockIdx.x * 64;
    int tx = tid & 15, ty = tid >> 4;
    float acc[4][4];
#pragma unroll
    for (int i = 0; i < 4; i++)
#pragma unroll
        for (int j = 0; j < 4; j++) acc[i][j] = 0.f;

    int ar = tid >> 2, ac2 = (tid & 3) * 2;
    int br = tid >> 5, bc = tid & 31;

    for (int k0 = 0; k0 < K; k0 += 8) {
        float2 a2 = *reinterpret_cast<const float2*>(A + (size_t)(row0 + ar) * K + k0 + ac2);
        As[ac2][ar] = a2.x;
        As[ac2 + 1][ar] = a2.y;
        float w0 = (col0 + bc < N)      ? W[(size_t)(k0 + br) * N + col0 + bc]      : 0.f;
        float w1 = (col0 + bc + 32 < N) ? W[(size_t)(k0 + br) * N + col0 + bc + 32] : 0.f;
        Bs[br][bc] = w0;
        Bs[br][bc + 32] = w1;
        __syncthreads();
#pragma unroll
        for (int kk = 0; kk < 8; kk++) {
            float av[4], bv[4];
#pragma unroll
            for (int i = 0; i < 4; i++) av[i] = As[kk][ty * 4 + i];
#pragma unroll
            for (int j = 0; j < 4; j++) bv[j] = Bs[kk][tx * 4 + j];
#pragma unroll
            for (int i = 0; i < 4; i++)
#pragma unroll
                for (int j = 0; j < 4; j++) acc[i][j] += av[i] * bv[j];
        }
        __syncthreads();
    }
#pragma unroll
    for (int i = 0; i < 4; i++) {
        int r = row0 + ty * 4 + i;
        if (r >= M) continue;
#pragma unroll
        for (int j = 0; j < 4; j++) {
            int c = col0 + tx * 4 + j;
            if (c >= N) continue;
            float val = acc[i][j] + cadd;
            if (bias) val += bias[c];
            size_t idx = (size_t)r * N + c;
            if (flags & 1) val += C[idx];
            if (flags & 2) val = fmaxf(val, 0.f);
            C[idx] = val;
        }
    }
}

// ---------- stats from f32 x: writes XB (bf16) + (mu, inv) per row ----------
__global__ void statx_kernel(const float* __restrict__ x, bf16* __restrict__ xb,
                             float2* __restrict__ st, int rows)
{
    int warp = blockIdx.x * (blockDim.x >> 5) + (threadIdx.x >> 5);
    if (warp >= rows) return;
    int lane = threadIdx.x & 31;
    const float4* xr = reinterpret_cast<const float4*>(x + (size_t)warp * DD);
    float4 v[4];
    float s1 = 0.f, s2 = 0.f;
#pragma unroll
    for (int i = 0; i < 4; i++) {
        v[i] = xr[i * 32 + lane];
        s1 += v[i].x + v[i].y + v[i].z + v[i].w;
        s2 += v[i].x * v[i].x + v[i].y * v[i].y + v[i].z * v[i].z + v[i].w * v[i].w;
    }
#pragma unroll
    for (int o = 16; o; o >>= 1) {
        s1 += __shfl_xor_sync(0xffffffffu, s1, o);
        s2 += __shfl_xor_sync(0xffffffffu, s2, o);
    }
    float mu = s1 * (1.f / DD);
    float inv = rsqrtf(s2 * (1.f / DD) - mu * mu + 1e-5f);
    uint2* orow = reinterpret_cast<uint2*>(xb + (size_t)warp * DD);
#pragma unroll
    for (int i = 0; i < 4; i++) {
        __nv_bfloat162 p0 = __floats2bfloat162_rn(v[i].x, v[i].y);
        __nv_bfloat162 p1 = __floats2bfloat162_rn(v[i].z, v[i].w);
        uint2 pk;
        pk.x = *reinterpret_cast<uint32_t*>(&p0);
        pk.y = *reinterpret_cast<uint32_t*>(&p1);
        orow[i * 32 + lane] = pk;
    }
    if (lane == 0) st[warp] = make_float2(mu, inv);
}

// ---------- stats from bf16 rows ----------
__global__ void statb_kernel(const bf16* __restrict__ x, float2* __restrict__ st, int rows)
{
    int warp = blockIdx.x * (blockDim.x >> 5) + (threadIdx.x >> 5);
    if (warp >= rows) return;
    int lane = threadIdx.x & 31;
    const uint2* xr = reinterpret_cast<const uint2*>(x + (size_t)warp * DD);
    float s1 = 0.f, s2 = 0.f;
#pragma unroll
    for (int i = 0; i < 4; i++) {
        uint2 pk = xr[i * 32 + lane];
        __nv_bfloat162 p0 = *reinterpret_cast<__nv_bfloat162*>(&pk.x);
        __nv_bfloat162 p1 = *reinterpret_cast<__nv_bfloat162*>(&pk.y);
        float t0 = __bfloat162float(p0.x), t1 = __bfloat162float(p0.y);
        float t2 = __bfloat162float(p1.x), t3 = __bfloat162float(p1.y);
        s1 += t0 + t1 + t2 + t3;
        s2 += t0 * t0 + t1 * t1 + t2 * t2 + t3 * t3;
    }
#pragma unroll
    for (int o = 16; o; o >>= 1) {
        s1 += __shfl_xor_sync(0xffffffffu, s1, o);
        s2 += __shfl_xor_sync(0xffffffffu, s2, o);
    }
    float mu = s1 * (1.f / DD);
    float inv = rsqrtf(s2 * (1.f / DD) - mu * mu + 1e-5f);
    if (lane == 0) st[warp] = make_float2(mu, inv);
}

// ---------- attention: q/k/v from src qkv buffer + memory kvm ----------
__global__ void attn_kernel(const float* __restrict__ qkv, const float* __restrict__ kvm,
                            const float* __restrict__ p, const float* __restrict__ uu,
                            const float* __restrict__ vvec, bf16* __restrict__ av)
{
    int b = blockIdx.x, h = blockIdx.y;
    __shared__ float Ks[JJ][33];
    __shared__ float Vs[JJ][33];
    __shared__ float att[4][JJ];
    __shared__ float qsu[4][32];
    __shared__ float qsv[4][32];
    int tid = threadIdx.x;
    for (int idx = tid; idx < JJ * 32; idx += 128) {
        int j = idx >> 5, d = idx & 31;
        const float* row;
        if (j < MM)
            row = kvm + ((size_t)j * BB + b) * 128 + h * 32 + d;
        else
            row = qkv + ((size_t)(j - MM) * BB + b) * 192 + 64 + h * 32 + d;
        Ks[j][d] = row[0];
        Vs[j][d] = row[64];
    }
    __syncthreads();
    int warp = tid >> 5, lane = tid & 31;
    float ul = uu[h * 32 + lane], vl = vvec[h * 32 + lane];
    for (int i = warp; i < TT; i += 4) {
        float qv = qkv[((size_t)i * BB + b) * 192 + h * 32 + lane];
        qsu[warp][lane] = qv + ul;
        qsv[warp][lane] = qv + vl;
        __syncwarp();
        int jmax = i + MM;
        float sv[5], smax = -1e30f;
        int cnt = 0;
        for (int j = lane; j <= jmax; j += 32) {
            const float* prow = p + (size_t)(j + TT - 1 - i) * 64 + h * 32;
            float s = 0.f;
#pragma unroll
            for (int d = 0; d < 32; d++)
                s += qsu[warp][d] * Ks[j][d] + qsv[warp][d] * prow[d];
            s *= 0.1767766952966369f;
            sv[cnt++] = s;
            smax = fmaxf(smax, s);
        }
#pragma unroll
        for (int o = 16; o; o >>= 1) smax = fmaxf(smax, __shfl_xor_sync(0xffffffffu, smax, o));
        float sum = 0.f; cnt = 0;
        for (int j = lane; j <= jmax; j += 32) {
            float e = __expf(sv[cnt++] - smax);
            att[warp][j] = e;
            sum += e;
        }
#pragma unroll
        for (int o = 16; o; o >>= 1) sum += __shfl_xor_sync(0xffffffffu, sum, o);
        float inv = 1.f / sum;
        __syncwarp();
        float acc = 0.f;
#pragma unroll 4
        for (int j = 0; j <= jmax; j++) acc += att[warp][j] * Vs[j][lane];
        av[((size_t)i * BB + b) * 64 + h * 32 + lane] = __float2bfloat16(acc * inv);
        __syncwarp();
    }
}

// ---------- mega prep (optional per-k scale on transpose) ----------
__device__ __forceinline__ void tpose_tile(const float* __restrict__ in, bf16* __restrict__ out,
                                           int K, int N, const float* __restrict__ scale)
{
    __shared__ float t[32][33];
    int k0 = blockIdx.y * 32, n0 = blockIdx.x * 32;
    if (k0 >= K || n0 >= N) return;
    int x = threadIdx.x, y = threadIdx.y;
    for (int i = y; i < 32; i += 8)
        t[i][x] = in[(size_t)(k0 + i) * N + n0 + x];
    __syncthreads();
    float s = scale ? scale[k0 + x] : 1.f;
    for (int i = y; i < 32; i += 8)
        out[(size_t)(n0 + i) * K + k0 + x] = __float2bfloat16(s * t[x][i]);
}

__global__ void megaprep_kernel(const float* __restrict__ g1W, const float* __restrict__ g2W,
                                const float* __restrict__ Wq, const float* __restrict__ Wkv,
                                const float* __restrict__ ffW1, const float* __restrict__ Wp,
                                const float* __restrict__ memory,
                                const float* __restrict__ ln1g, const float* __restrict__ ln2g)
{
    int z = blockIdx.z;
    if (z < 12) {
        const float* in = ((z < 6) ? g1W : g2W) + (size_t)(z % 6) * DD * DD;
        bf16* out = ((z < 6) ? gb_g1 : gb_g2) + (size_t)(z % 6) * DD * DD;
        tpose_tile(in, out, DD, DD, 0);
    } else if (z == 12) {
        tpose_tile(Wq, gb_wqkv, DD, 64, ln1g);
    } else if (z == 13) {
        tpose_tile(Wkv, gb_wqkv + 64 * DD, DD, 128, ln1g);
    } else if (z == 14) {
        tpose_tile(Wkv, gb_wkvm, DD, 128, 0);
    } else if (z == 15) {
        tpose_tile(ffW1, gb_ff1, DD, DFF, ln2g);
    } else if (z == 16) {
        int bid = blockIdx.y * 16 + blockIdx.x;
        int tid = threadIdx.y * 32 + threadIdx.x;
        const int n4 = MROW * DD / 4;
        for (int i = bid * 256 + tid; i < n4; i += 256 * 256) {
            float4 v = reinterpret_cast<const float4*>(memory)[i];
            __nv_bfloat162* o = reinterpret_cast<__nv_bfloat162*>(gb_mem + (size_t)i * 4);
            o[0] = __floats2bfloat162_rn(v.x, v.y);
            o[1] = __floats2bfloat162_rn(v.z, v.w);
        }
    } else {
        int jj = blockIdx.y * 16 + blockIdx.x;
        if (jj >= JJ) return;
        __shared__ float pe[DD];
        int tid = threadIdx.y * 32 + threadIdx.x;
        float pos = (float)(JJ - 1 - jj);
        for (int d = tid; d < DD; d += 256) {
            int i = (d < 256) ? d : d - 256;
            float f = __expf(-(float)(2 * i) * (1.f / 512.f) * 9.210340371976184f);
            float a = pos * f;
            pe[d] = (d < 256) ? sinf(a) : cosf(a);
        }
        __syncthreads();
        if (tid < 64) {
            float acc = 0.f;
            for (int d = 0; d < DD; d++) acc += pe[d] * Wp[d * 64 + tid];
            g_p[jj * 64 + tid] = acc;
        }
    }
}

// ---------- LN-fold column constants: cg[n] = sum_d g_d W[d,n]; cbb[n] = sum_d b_d W[d,n] (+ff_b1) ----------
__global__ void cgb_kernel(const float* __restrict__ Wq, const float* __restrict__ Wkv,
                           const float* __restrict__ ffW1,
                           const float* __restrict__ g1, const float* __restrict__ b1,
                           const float* __restrict__ g2, const float* __restrict__ b2,
                           const float* __restrict__ ffb1,
                           float* __restrict__ cg, float* __restrict__ cbb)
{
    int blk = blockIdx.x;      // 0: Wq cols; 1,2: Wkv halves; 3: ffW1
    int t = threadIdx.x;       // 0..63
    float sg = 0.f, sb = 0.f;
    if (blk == 0) {
        for (int d = 0; d < DD; d++) {
            float w = Wq[(size_t)d * 64 + t];
            sg += g1[d] * w; sb += b1[d] * w;
        }
        cg[t] = sg; cbb[t] = sb;
    } else if (blk <= 2) {
        int c = (blk - 1) * 64 + t;
        for (int d = 0; d < DD; d++) {
            float w = Wkv[(size_t)d * 128 + c];
            sg += g1[d] * w; sb += b1[d] * w;
        }
        cg[64 + c] = sg; cbb[64 + c] = sb;
    } else {
        for (int d = 0; d < DD; d++) {
            float w = ffW1[(size_t)d * DFF + t];
            sg += g2[d] * w; sb += b2[d] * w;
        }
        cg[192 + t] = sg; cbb[192 + t] = sb + ffb1[t];
    }
}

// ---------- folded-weight precompute ----------
__global__ void pregemm_kernel(const float* __restrict__ Wout, const float* __restrict__ ffW2,
                               const float* __restrict__ g1W, const float* __restrict__ g2W)
{
    __shared__ float sG[64][33];
    const int slot[3] = {0, 2, 4};
    int m = blockIdx.z;
    const float* A = (m < 3) ? Wout : ffW2;
    const float* G = ((m < 3) ? g1W : g2W) + (size_t)slot[m % 3] * DD * DD;
    bf16* out = gb_cw + (size_t)m * DD * 64;
    int n0 = blockIdx.x * 32, k0 = blockIdx.y * 8;
    int tx = threadIdx.x, ty = threadIdx.y;
    int tid = ty * 32 + tx;
    float acc = 0.f;
    for (int dc = 0; dc < 8; dc++) {
        __syncthreads();
        for (int idx = tid; idx < 64 * 32; idx += 256) {
            int i = idx >> 5, j = idx & 31;
            sG[i][j] = G[(size_t)(dc * 64 + i) * DD + n0 + j];
        }
        __syncthreads();
        const float* Ar = A + (size_t)(k0 + ty) * DD + dc * 64;
#pragma unroll 16
        for (int i = 0; i < 64; i++) acc += Ar[i] * sG[i][tx];
    }
    out[(size_t)(n0 + tx) * 64 + (k0 + ty)] = __float2bfloat16(acc);
}

// ---------- gate-2 combined bias ----------
__global__ void bc2_kernel(const float* __restrict__ ffb2, const float* __restrict__ g2W,
                           const float* __restrict__ g2b, float* __restrict__ bc)
{
    const int slot[3] = {0, 2, 4};
    int m = blockIdx.x;
    int n = threadIdx.x;
    const float* G = g2W + (size_t)slot[m] * DD * DD;
    float acc = g2b[(2 * m) * DD + n] + g2b[(2 * m + 1) * DD + n];
    for (int d = 0; d < DD; d++) acc += ffb2[d] * G[(size_t)d * DD + n];
    bc[m * DD + n] = acc;
}

// ---------- mean pool from bf16 ----------
__global__ void meanpool_bf_kernel(const bf16* __restrict__ in, float* __restrict__ ts)
{
    int idx = blockIdx.x * blockDim.x + threadIdx.x;
    const int n2 = BB * DD / 2;
    if (idx >= n2) return;
    float s0 = 0.f, s1 = 0.f;
    for (int t = 0; t < TT; t++) {
        __nv_bfloat162 v = *reinterpret_cast<const __nv_bfloat162*>(in + (size_t)t * BB * DD + idx * 2);
        s0 += __bfloat162float(v.x);
        s1 += __bfloat162float(v.y);
    }
    const float inv = 1.f / TT;
    *reinterpret_cast<float2*>(ts + (size_t)idx * 2) = make_float2(s0 * inv, s1 * inv);
}

// ---------- final head ----------
__global__ void final_kernel(const float* __restrict__ h3, const float* __restrict__ w,
                             const float* __restrict__ bb, float* __restrict__ out)
{
    int row = blockIdx.x * 4 + (threadIdx.x >> 5);
    int lane = threadIdx.x & 31;
    if (row >= BB) return;
    float s = 0.f;
    for (int k = lane; k < 300; k += 32) s += h3[(size_t)row * 300 + k] * w[k];
#pragma unroll
    for (int o = 16; o; o >>= 1) s += __shfl_xor_sync(0xffffffffu, s, o);
    if (lane == 0) out[row] = fmaxf(s + bb[0], 0.f);
}

// ---------- host ----------
static inline void launch_tc(const bf16* A0, const bf16* W0, int K0,
                             const bf16* A1, const bf16* W1, int K1,
                             int M, int N, int NT,
                             float* Cf, bf16* Cb,
                             const float* b1, const float* b2, float cadd,
                             const bf16* zpre, const bf16* aux, int mode,
                             const float2* rstat = 0)
{
    dim3 grid(N / NT, M / 128);
    if (NT == 128) {
        size_t dsz = 3 * (size_t)(128 + 128) * 144;
        bgemm<128><<<grid, 256, dsz>>>(A0, W0, K0, A1, W1, K1, N, Cf, Cb, b1, b2, cadd, zpre, aux, rstat, mode);
    } else {
        size_t dsz = 3 * (size_t)(128 + 64) * 144;
        bgemm<64><<<grid, 256, dsz>>>(A0, W0, K0, A1, W1, K1, N, Cf, Cb, b1, b2, cadd, zpre, aux, rstat, mode);
    }
}
static inline void launch_sgemm(const float* A, const float* W, float* C,
                                int M, int N, int K, const float* bias, float cadd, int flags)
{
    dim3 grid((N + 63) / 64, (M + 63) / 64);
    sgemm64_kernel<<<grid, 256>>>(A, W, C, M, N, K, bias, cadd, flags);
}

extern "C" void kernel_launch(void* const* d_in, const int* in_sizes, int n_in,
                              void* d_out, int out_size)
{
    const float* x      = (const float*)d_in[0];
    const float* action = (const float*)d_in[1];
    const float* memory = (const float*)d_in[2];
    const float* W_q    = (const float*)d_in[3];
    const float* W_kv   = (const float*)d_in[4];
    const float* W_p    = (const float*)d_in[5];
    const float* W_out  = (const float*)d_in[6];
    const float* u      = (const float*)d_in[7];
    const float* v      = (const float*)d_in[8];
    const float* ln1_g  = (const float*)d_in[9];
    const float* ln1_b  = (const float*)d_in[10];
    const float* ln2_g  = (const float*)d_in[11];
    const float* ln2_b  = (const float*)d_in[12];
    const float* ff_W1  = (const float*)d_in[13];
    const float* ff_b1  = (const float*)d_in[14];
    const float* ff_W2  = (const float*)d_in[15];
    const float* ff_b2  = (const float*)d_in[16];
    const float* g1W    = (const float*)d_in[17];
    const float* g1b    = (const float*)d_in[18];
    const float* g2W    = (const float*)d_in[19];
    const float* g2b    = (const float*)d_in[20];
    const float* d1W    = (const float*)d_in[21];
    const float* d1b    = (const float*)d_in[22];
    const float* d2W    = (const float*)d_in[23];
    const float* d2b    = (const float*)d_in[24];
    const float* d3W    = (const float*)d_in[25];
    const float* d3b    = (const float*)d_in[26];
    const float* d4W    = (const float*)d_in[27];
    const float* d4b    = (const float*)d_in[28];

    cudaFuncSetAttribute(bgemm<128>, cudaFuncAttributeMaxDynamicSharedMemorySize, 111000);
    cudaFuncSetAttribute(bgemm<64>,  cudaFuncAttributeMaxDynamicSharedMemorySize, 84000);

    float *QKV, *KVM, *P, *TS, *H1, *H2, *H3, *BC2, *CG, *CBB;
    float2 *ST1, *ST2;
    bf16 *XB, *MEMB, *RXB, *ZB, *SRCB, *FFHB, *AVB;
    bf16 *WQKVT, *WKVMT, *G1T, *G2T, *FF1G, *CW;
    cudaGetSymbolAddress((void**)&QKV,  g_qkv);
    cudaGetSymbolAddress((void**)&KVM,  g_kvm);
    cudaGetSymbolAddress((void**)&P,    g_p);
    cudaGetSymbolAddress((void**)&TS,   g_ts);
    cudaGetSymbolAddress((void**)&H1,   g_h1);
    cudaGetSymbolAddress((void**)&H2,   g_h2);
    cudaGetSymbolAddress((void**)&H3,   g_h3);
    cudaGetSymbolAddress((void**)&BC2,  g_bc2);
    cudaGetSymbolAddress((void**)&CG,   g_cg);
    cudaGetSymbolAddress((void**)&CBB,  g_cbb);
    cudaGetSymbolAddress((void**)&ST1,  g_st1);
    cudaGetSymbolAddress((void**)&ST2,  g_st2);
    cudaGetSymbolAddress((void**)&XB,   gb_x);
    cudaGetSymbolAddress((void**)&MEMB, gb_mem);
    cudaGetSymbolAddress((void**)&RXB,  gb_rx);
    cudaGetSymbolAddress((void**)&ZB,   gb_z);
    cudaGetSymbolAddress((void**)&SRCB, gb_src);
    cudaGetSymbolAddress((void**)&FFHB, gb_ffh);
    cudaGetSymbolAddress((void**)&AVB,  gb_av);
    cudaGetSymbolAddress((void**)&WQKVT,gb_wqkv);
    cudaGetSymbolAddress((void**)&WKVMT,gb_wkvm);
    cudaGetSymbolAddress((void**)&G1T,  gb_g1);
    cudaGetSymbolAddress((void**)&G2T,  gb_g2);
    cudaGetSymbolAddress((void**)&FF1G, gb_ff1);
    cudaGetSymbolAddress((void**)&CW,   gb_cw);

    const size_t SZ = (size_t)DD * DD;
    const size_t CWS = (size_t)DD * 64;

    // prep
    megaprep_kernel<<<dim3(16, 16, 18), dim3(32, 8)>>>(
        g1W, g2W, W_q, W_kv, ff_W1, W_p, memory, ln1_g, ln2_g);
    pregemm_kernel<<<dim3(16, 8, 6), dim3(32, 8)>>>(W_out, ff_W2, g1W, g2W);
    bc2_kernel<<<3, DD>>>(ff_b2, g2W, g2b, BC2);
    cgb_kernel<<<4, 64>>>(W_q, W_kv, ff_W1, ln1_g, ln1_b, ln2_g, ln2_b, ff_b1, CG, CBB);

    // x stats + bf16 copy
    statx_kernel<<<NROW / 8, 256>>>(x, XB, ST1, NROW);

    // qkv (LN1 folded): src rows only, mode 6
    launch_tc(XB, WQKVT, DD, 0, 0, 0, NROW, 192, 64, QKV, 0, CG, CBB, 0.f, 0, 0, 6, ST1);

    // memory kv (raw weights)
    launch_tc(MEMB, WKVMT, DD, 0, 0, 0, MROW, 128, 128, KVM, 0, 0, 0, 0.f, 0, 0, 0);

    // attention -> AVB (bf16)
    attn_kernel<<<dim3(BB, HH), 128>>>(QKV, KVM, P, u, v, AVB);

    // gate 1 (y-side folded through W_out; K = 64 + 512)
    launch_tc(AVB, CW + 0 * CWS, 64, XB, G1T + 1 * SZ, DD, NROW, DD, 128,
              0, RXB, g1b + 0 * DD, g1b + 1 * DD, 0.f, 0, XB, 4);
    launch_tc(AVB, CW + 1 * CWS, 64, XB, G1T + 3 * SZ, DD, NROW, DD, 128,
              0, ZB, g1b + 2 * DD, g1b + 3 * DD, -BG, 0, 0, 2);
    launch_tc(AVB, CW + 2 * CWS, 64, RXB, G1T + 5 * SZ, DD, NROW, DD, 128,
              0, SRCB, g1b + 4 * DD, g1b + 5 * DD, 0.f, ZB, XB, 5);

    // src stats, then ffh (LN2 folded, relu, bf16)
    statb_kernel<<<NROW / 8, 256>>>(SRCB, ST2, NROW);
    launch_tc(SRCB, FF1G, DD, 0, 0, 0, NROW, DFF, 64, 0, FFHB, CG + 192, CBB + 192, 0.f, 0, 0, 7, ST2);

    // gate 2 (y-side = ff folded through ff_W2)
    launch_tc(FFHB, CW + 3 * CWS, 64, SRCB, G2T + 1 * SZ, DD, NROW, DD, 128,
              0, RXB, BC2 + 0 * DD, 0, 0.f, 0, SRCB, 4);
    launch_tc(FFHB, CW + 4 * CWS, 64, SRCB, G2T + 3 * SZ, DD, NROW, DD, 128,
              0, ZB, BC2 + 1 * DD, 0, -BG, 0, 0, 2);
    launch_tc(FFHB, CW + 5 * CWS, 64, RXB, G2T + 5 * SZ, DD, NROW, DD, 128,
              0, XB, BC2 + 2 * DD, 0, 0.f, ZB, SRCB, 5);

    // mean pool (bf16 in, f32 out)
    meanpool_bf_kernel<<<(BB * DD / 2 + 255) / 256, 256>>>(XB, TS);

    // critic head (exact fp32)
    launch_sgemm(TS, d1W, H1, BB, 1024, DD, d1b, 0.f, 2);
    launch_sgemm(H1, d2W, H2, BB, 512, 1024, nullptr, 0.f, 0);
    launch_sgemm(action, d2W + (size_t)1024 * 512, H2, BB, 512, ACT, d2b, 0.f, 3);
    launch_sgemm(H2, d3W, H3, BB, 300, DD, d3b, 0.f, 2);
    final_kernel<<<BB / 4, 128>>>(H3, d4W, d4b, (float*)d_out);
}

// round 17
// speedup vs baseline: 1.0116x; 1.0116x over previous
#include <cuda_runtime.h>
#include <cuda_bf16.h>
#include <math.h>
#include <stdint.h>

#define TT   128
#define BB   512
#define DD   512
#define MM   6
#define JJ   (TT + MM)
#define HH   2
#define DFF  64
#define ACT  64
#define NROW (TT * BB)
#define MROW (MM * BB)
#define BG   0.1f

typedef __nv_bfloat16 bf16;

// ---------- static scratch ----------
__device__ __align__(256) float g_qkv[NROW * 192];
__device__ __align__(256) float g_kvm[MROW * 128];
__device__ __align__(256) float g_p  [JJ * 64];
__device__ __align__(256) float g_ts [BB * DD];
__device__ __align__(256) float g_h1 [BB * 1024];
__device__ __align__(256) float g_h2 [BB * 512];
__device__ __align__(256) float g_h3 [BB * 300];
__device__ __align__(256) float g_bc2[3 * DD];
__device__ __align__(256) float g_cg [256];
__device__ __align__(256) float g_cbb[256];
__device__ __align__(256) float2 g_st1[NROW];
__device__ __align__(256) float2 g_st2[NROW];
__device__ __align__(256) bf16 gb_x   [NROW * DD];
__device__ __align__(256) bf16 gb_mem [MROW * DD];
__device__ __align__(256) bf16 gb_rx  [NROW * DD];
__device__ __align__(256) bf16 gb_z   [NROW * DD];
__device__ __align__(256) bf16 gb_src [NROW * DD];
__device__ __align__(256) bf16 gb_ffh [NROW * DFF];
__device__ __align__(256) bf16 gb_av  [NROW * 64];
__device__ __align__(256) bf16 gb_wqkv[192 * DD];   // LN1-g-scaled [Wq|Wkv]^T
__device__ __align__(256) bf16 gb_wkvm[128 * DD];   // raw Wkv^T (memory rows)
__device__ __align__(256) bf16 gb_g1  [6 * DD * DD];
__device__ __align__(256) bf16 gb_g2  [6 * DD * DD];
__device__ __align__(256) bf16 gb_ff1 [DFF * DD];   // LN2-g-scaled ff_W1^T
__device__ __align__(256) bf16 gb_cw  [6 * DD * 64];

// ---------- helpers ----------
__device__ __forceinline__ uint32_t s2u(const void* p) {
    return (uint32_t)__cvta_generic_to_shared(p);
}
__device__ __forceinline__ void cp16(uint32_t s, const void* g) {
    asm volatile("cp.async.cg.shared.global [%0], [%1], 16;" :: "r"(s), "l"(g));
}
__device__ __forceinline__ void cp_commit() { asm volatile("cp.async.commit_group;" ::: "memory"); }
__device__ __forceinline__ void cp_wait0()  { asm volatile("cp.async.wait_group 0;" ::: "memory"); }
__device__ __forceinline__ void cp_wait1()  { asm volatile("cp.async.wait_group 1;" ::: "memory"); }
__device__ __forceinline__ void ldsm4(uint32_t* r, uint32_t addr) {
    asm volatile("ldmatrix.sync.aligned.m8n8.x4.shared.b16 {%0,%1,%2,%3}, [%4];"
                 : "=r"(r[0]), "=r"(r[1]), "=r"(r[2]), "=r"(r[3]) : "r"(addr));
}
__device__ __forceinline__ void mma_bf16(float* c, const uint32_t* a, const uint32_t* b) {
    asm volatile(
        "mma.sync.aligned.m16n8k16.row.col.f32.bf16.bf16.f32 "
        "{%0,%1,%2,%3}, {%4,%5,%6,%7}, {%8,%9}, {%0,%1,%2,%3};"
        : "+f"(c[0]), "+f"(c[1]), "+f"(c[2]), "+f"(c[3])
        : "r"(a[0]), "r"(a[1]), "r"(a[2]), "r"(a[3]), "r"(b[0]), "r"(b[1]));
}
__device__ __forceinline__ float tanh_fast(float x) {
    float r;
    asm("tanh.approx.f32 %0, %1;" : "=f"(r) : "f"(x));
    return r;
}
__device__ __forceinline__ float sig_fast(float x) {
    return fmaf(0.5f, tanh_fast(0.5f * x), 0.5f);
}

// ---------- bf16 dual-source tensor GEMM ----------
// modes: 0 f32 | 2 bf16 | 3 bf16 relu | 4 bf16 = sigmoid(v)*aux
//        5 gate combine | 6 f32 LN-fold (rstat,cg,cbb) | 7 bf16 relu LN-fold

template<int NT>
__global__ __launch_bounds__(256, 2)
void bgemm(const bf16* __restrict__ A0, const bf16* __restrict__ W0, int K0,
           const bf16* __restrict__ A1, const bf16* __restrict__ W1, int K1,
           int N,
           float* __restrict__ Cf, bf16* __restrict__ Cb,
           const float* __restrict__ bias1, const float* __restrict__ bias2,
           float cadd, const bf16* __restrict__ zpre, const bf16* __restrict__ aux,
           const float2* __restrict__ rstat, int mode)
{
    extern __shared__ char dsm[];
    constexpr int NTI = NT / 32;
    constexpr int STG = (128 + NT) * 144;

    const int tid  = threadIdx.x;
    const int warp = tid >> 5, lane = tid & 31;
    const int grp  = lane >> 2, thr = lane & 3;
    const int wm   = warp & 1,  wn  = warp >> 1;
    const int m_base = wm * 64;
    const int n_base = wn * (NT / 4);
    const int row0 = blockIdx.y * 128;
    const int col0 = blockIdx.x * NT;
    const uint32_t sb = s2u(dsm);

    float acc[4][NTI][4];
#pragma unroll
    for (int i = 0; i < 4; i++)
#pragma unroll
        for (int j = 0; j < NTI; j++)
#pragma unroll
            for (int r = 0; r < 4; r++) acc[i][j][r] = 0.f;

    const int NC0 = K0 >> 6;
    const int NC  = NC0 + (K1 >> 6);

    auto load_stage = [&](int c, int buf) {
        const bf16 *a, *w; int k, kb;
        if (c < NC0) { a = A0; w = W0; k = K0; kb = c << 6; }
        else         { a = A1; w = W1; k = K1; kb = (c - NC0) << 6; }
        uint32_t ab = sb + (uint32_t)buf * STG;
#pragma unroll
        for (int i = 0; i < 4; i++) {
            int u = tid + i * 256;
            int r = u >> 3, cc = u & 7;
            cp16(ab + (uint32_t)(r * 144 + cc * 16),
                 a + (size_t)(row0 + r) * k + kb + cc * 8);
        }
        uint32_t bb = ab + 128u * 144u;
#pragma unroll
        for (int i = 0; i < NT / 32; i++) {
            int u = tid + i * 256;
            int r = u >> 3, cc = u & 7;
            cp16(bb + (uint32_t)(r * 144 + cc * 16),
                 w + (size_t)(col0 + r) * k + kb + cc * 8);
        }
        cp_commit();
    };

    load_stage(0, 0);
    if (NC > 1) load_stage(1, 1);

    for (int c = 0; c < NC; c++) {
        if (c == NC - 1) cp_wait0(); else cp_wait1();
        __syncthreads();
        if (c + 2 < NC) load_stage(c + 2, (c + 2) % 3);

        uint32_t ab = sb + (uint32_t)(c % 3) * STG;
        uint32_t bb = ab + 128u * 144u;

        const uint32_t a_lrow = (uint32_t)(lane & 15);
        const uint32_t a_koff = (uint32_t)((lane >> 4) << 3);
        const uint32_t b_cofs = (uint32_t)(((lane >> 4) << 3) + (lane & 7));
        const uint32_t b_koff = (uint32_t)(((lane >> 3) & 1) << 3);

#pragma unroll
        for (int ks = 0; ks < 4; ks++) {
            const int kc = ks * 16;
            uint32_t af[4][4], bfr[NTI][2];
#pragma unroll
            for (int mt = 0; mt < 4; mt++) {
                uint32_t addr = ab + (uint32_t)(m_base + mt * 16 + a_lrow) * 144u
                                   + (uint32_t)(kc + a_koff) * 2u;
                ldsm4(af[mt], addr);
            }
#pragma unroll
            for (int p = 0; p < NTI / 2; p++) {
                uint32_t col = (uint32_t)(n_base + p * 16) + b_cofs;
                uint32_t addr = bb + col * 144u + (uint32_t)(kc + b_koff) * 2u;
                uint32_t r[4];
                ldsm4(r, addr);
                bfr[2 * p][0]     = r[0]; bfr[2 * p][1]     = r[1];
                bfr[2 * p + 1][0] = r[2]; bfr[2 * p + 1][1] = r[3];
            }
#pragma unroll
            for (int mt = 0; mt < 4; mt++)
#pragma unroll
                for (int nt = 0; nt < NTI; nt++)
                    mma_bf16(acc[mt][nt], af[mt], bfr[nt]);
        }
    }

    // epilogue
#pragma unroll
    for (int mt = 0; mt < 4; mt++) {
#pragma unroll
        for (int nt = 0; nt < NTI; nt++) {
            int cbase = col0 + n_base + nt * 8 + thr * 2;
            if (mode >= 6) {
                float cg0 = bias1[cbase], cg1 = bias1[cbase + 1];
                float cb0 = bias2[cbase], cb1 = bias2[cbase + 1];
#pragma unroll
                for (int half = 0; half < 2; half++) {
                    int r = row0 + m_base + mt * 16 + grp + half * 8;
                    size_t idx = (size_t)r * N + cbase;
                    float2 st = rstat[r];
                    float off = -st.y * st.x;
                    float v0 = fmaf(st.y, acc[mt][nt][half * 2 + 0], fmaf(off, cg0, cb0));
                    float v1 = fmaf(st.y, acc[mt][nt][half * 2 + 1], fmaf(off, cg1, cb1));
                    if (mode == 6) {
                        *reinterpret_cast<float2*>(Cf + idx) = make_float2(v0, v1);
                    } else {
                        *reinterpret_cast<__nv_bfloat162*>(Cb + idx) =
                            __floats2bfloat162_rn(fmaxf(v0, 0.f), fmaxf(v1, 0.f));
                    }
                }
                continue;
            }
            float b0 = cadd, b1 = cadd;
            if (bias1) { b0 += bias1[cbase]; b1 += bias1[cbase + 1]; }
            if (bias2) { b0 += bias2[cbase]; b1 += bias2[cbase + 1]; }
#pragma unroll
            for (int half = 0; half < 2; half++) {
                int r = row0 + m_base + mt * 16 + grp + half * 8;
                size_t idx = (size_t)r * N + cbase;
                float v0 = acc[mt][nt][half * 2 + 0] + b0;
                float v1 = acc[mt][nt][half * 2 + 1] + b1;
                if (mode == 0) {
                    *reinterpret_cast<float2*>(Cf + idx) = make_float2(v0, v1);
                } else if (mode == 2) {
                    *reinterpret_cast<__nv_bfloat162*>(Cb + idx) = __floats2bfloat162_rn(v0, v1);
                } else if (mode == 3) {
                    *reinterpret_cast<__nv_bfloat162*>(Cb + idx) =
                        __floats2bfloat162_rn(fmaxf(v0, 0.f), fmaxf(v1, 0.f));
                } else if (mode == 4) {
                    __nv_bfloat162 a2 = *reinterpret_cast<const __nv_bfloat162*>(aux + idx);
                    *reinterpret_cast<__nv_bfloat162*>(Cb + idx) =
                        __floats2bfloat162_rn(sig_fast(v0) * __bfloat162float(a2.x),
                                              sig_fast(v1) * __bfloat162float(a2.y));
                } else {
                    __nv_bfloat162 z2 = *reinterpret_cast<const __nv_bfloat162*>(zpre + idx);
                    __nv_bfloat162 a2 = *reinterpret_cast<const __nv_bfloat162*>(aux + idx);
                    float z0 = sig_fast(__bfloat162float(z2.x));
                    float z1 = sig_fast(__bfloat162float(z2.y));
                    float o0 = (1.f - z0) * __bfloat162float(a2.x) + z0 * tanh_fast(v0);
                    float o1 = (1.f - z1) * __bfloat162float(a2.y) + z1 * tanh_fast(v1);
                    if (Cf) *reinterpret_cast<float2*>(Cf + idx) = make_float2(o0, o1);
                    if (Cb) *reinterpret_cast<__nv_bfloat162*>(Cb + idx) =
                        __floats2bfloat162_rn(o0, o1);
                }
            }
        }
    }
}

// ---------- exact fp32 GEMM, 64x64 tiles (critic head) ----------
__global__ void sgemm64_kernel(const float* __restrict__ A, const float* __restrict__ W,
                               float* __restrict__ C, int M, int N, int K,
                               const float* __restrict__ bias, float cadd, int flags)
{
    __shared__ float As[8][64];
    __shared__ float Bs[8][65];
    int tid = threadIdx.x;
    int row0 = blockIdx.y * 64, col0 = blockIdx.x * 64;
    int tx = tid & 15, ty = tid >> 4;
    float acc[4][4];
#pragma unroll
    for (int i = 0; i < 4; i++)
#pragma unroll
        for (int j = 0; j < 4; j++) acc[i][j] = 0.f;

    int ar = tid >> 2, ac2 = (tid & 3) * 2;
    int br = tid >> 5, bc = tid & 31;

    for (int k0 = 0; k0 < K; k0 += 8) {
        float2 a2 = *reinterpret_cast<const float2*>(A + (size_t)(row0 + ar) * K + k0 + ac2);
        As[ac2][ar] = a2.x;
        As[ac2 + 1][ar] = a2.y;
        float w0 = (col0 + bc < N)      ? W[(size_t)(k0 + br) * N + col0 + bc]      : 0.f;
        float w1 = (col0 + bc + 32 < N) ? W[(size_t)(k0 + br) * N + col0 + bc + 32] : 0.f;
        Bs[br][bc] = w0;
        Bs[br][bc + 32] = w1;
        __syncthreads();
#pragma unroll
        for (int kk = 0; kk < 8; kk++) {
            float av[4], bv[4];
#pragma unroll
            for (int i = 0; i < 4; i++) av[i] = As[kk][ty * 4 + i];
#pragma unroll
            for (int j = 0; j < 4; j++) bv[j] = Bs[kk][tx * 4 + j];
#pragma unroll
            for (int i = 0; i < 4; i++)
#pragma unroll
                for (int j = 0; j < 4; j++) acc[i][j] += av[i] * bv[j];
        }
        __syncthreads();
    }
#pragma unroll
    for (int i = 0; i < 4; i++) {
        int r = row0 + ty * 4 + i;
        if (r >= M) continue;
#pragma unroll
        for (int j = 0; j < 4; j++) {
            int c = col0 + tx * 4 + j;
            if (c >= N) continue;
            float val = acc[i][j] + cadd;
            if (bias) val += bias[c];
            size_t idx = (size_t)r * N + c;
            if (flags & 1) val += C[idx];
            if (flags & 2) val = fmaxf(val, 0.f);
            C[idx] = val;
        }
    }
}

// ---------- stats from f32 x: writes XB (bf16) + (mu, inv) per row ----------
__global__ void statx_kernel(const float* __restrict__ x, bf16* __restrict__ xb,
                             float2* __restrict__ st, int rows)
{
    int warp = blockIdx.x * (blockDim.x >> 5) + (threadIdx.x >> 5);
    if (warp >= rows) return;
    int lane = threadIdx.x & 31;
    const float4* xr = reinterpret_cast<const float4*>(x + (size_t)warp * DD);
    float4 v[4];
    float s1 = 0.f, s2 = 0.f;
#pragma unroll
    for (int i = 0; i < 4; i++) {
        v[i] = xr[i * 32 + lane];
        s1 += v[i].x + v[i].y + v[i].z + v[i].w;
        s2 += v[i].x * v[i].x + v[i].y * v[i].y + v[i].z * v[i].z + v[i].w * v[i].w;
    }
#pragma unroll
    for (int o = 16; o; o >>= 1) {
        s1 += __shfl_xor_sync(0xffffffffu, s1, o);
        s2 += __shfl_xor_sync(0xffffffffu, s2, o);
    }
    float mu = s1 * (1.f / DD);
    float inv = rsqrtf(s2 * (1.f / DD) - mu * mu + 1e-5f);
    uint2* orow = reinterpret_cast<uint2*>(xb + (size_t)warp * DD);
#pragma unroll
    for (int i = 0; i < 4; i++) {
        __nv_bfloat162 p0 = __floats2bfloat162_rn(v[i].x, v[i].y);
        __nv_bfloat162 p1 = __floats2bfloat162_rn(v[i].z, v[i].w);
        uint2 pk;
        pk.x = *reinterpret_cast<uint32_t*>(&p0);
        pk.y = *reinterpret_cast<uint32_t*>(&p1);
        orow[i * 32 + lane] = pk;
    }
    if (lane == 0) st[warp] = make_float2(mu, inv);
}

// ---------- stats from bf16 rows ----------
__global__ void statb_kernel(const bf16* __restrict__ x, float2* __restrict__ st, int rows)
{
    int warp = blockIdx.x * (blockDim.x >> 5) + (threadIdx.x >> 5);
    if (warp >= rows) return;
    int lane = threadIdx.x & 31;
    const uint2* xr = reinterpret_cast<const uint2*>(x + (size_t)warp * DD);
    float s1 = 0.f, s2 = 0.f;
#pragma unroll
    for (int i = 0; i < 4; i++) {
        uint2 pk = xr[i * 32 + lane];
        __nv_bfloat162 p0 = *reinterpret_cast<__nv_bfloat162*>(&pk.x);
        __nv_bfloat162 p1 = *reinterpret_cast<__nv_bfloat162*>(&pk.y);
        float t0 = __bfloat162float(p0.x), t1 = __bfloat162float(p0.y);
        float t2 = __bfloat162float(p1.x), t3 = __bfloat162float(p1.y);
        s1 += t0 + t1 + t2 + t3;
        s2 += t0 * t0 + t1 * t1 + t2 * t2 + t3 * t3;
    }
#pragma unroll
    for (int o = 16; o; o >>= 1) {
        s1 += __shfl_xor_sync(0xffffffffu, s1, o);
        s2 += __shfl_xor_sync(0xffffffffu, s2, o);
    }
    float mu = s1 * (1.f / DD);
    float inv = rsqrtf(s2 * (1.f / DD) - mu * mu + 1e-5f);
    if (lane == 0) st[warp] = make_float2(mu, inv);
}

// ---------- attention ----------
__global__ void attn_kernel(const float* __restrict__ qkv, const float* __restrict__ kvm,
                            const float* __restrict__ p, const float* __restrict__ uu,
                            const float* __restrict__ vvec, bf16* __restrict__ av)
{
    int b = blockIdx.x, h = blockIdx.y;
    __shared__ float Ks[JJ][33];
    __shared__ float Vs[JJ][33];
    __shared__ float att[4][JJ];
    __shared__ float qsu[4][32];
    __shared__ float qsv[4][32];
    int tid = threadIdx.x;
    for (int idx = tid; idx < JJ * 32; idx += 128) {
        int j = idx >> 5, d = idx & 31;
        const float* row;
        if (j < MM)
            row = kvm + ((size_t)j * BB + b) * 128 + h * 32 + d;
        else
            row = qkv + ((size_t)(j - MM) * BB + b) * 192 + 64 + h * 32 + d;
        Ks[j][d] = row[0];
        Vs[j][d] = row[64];
    }
    __syncthreads();
    int warp = tid >> 5, lane = tid & 31;
    float ul = uu[h * 32 + lane], vl = vvec[h * 32 + lane];
    for (int i = warp; i < TT; i += 4) {
        float qv = qkv[((size_t)i * BB + b) * 192 + h * 32 + lane];
        qsu[warp][lane] = qv + ul;
        qsv[warp][lane] = qv + vl;
        __syncwarp();
        int jmax = i + MM;
        float sv[5], smax = -1e30f;
        int cnt = 0;
        for (int j = lane; j <= jmax; j += 32) {
            const float* prow = p + (size_t)(j + TT - 1 - i) * 64 + h * 32;
            float s = 0.f;
#pragma unroll
            for (int d = 0; d < 32; d++)
                s += qsu[warp][d] * Ks[j][d] + qsv[warp][d] * prow[d];
            s *= 0.1767766952966369f;
            sv[cnt++] = s;
            smax = fmaxf(smax, s);
        }
#pragma unroll
        for (int o = 16; o; o >>= 1) smax = fmaxf(smax, __shfl_xor_sync(0xffffffffu, smax, o));
        float sum = 0.f; cnt = 0;
        for (int j = lane; j <= jmax; j += 32) {
            float e = __expf(sv[cnt++] - smax);
            att[warp][j] = e;
            sum += e;
        }
#pragma unroll
        for (int o = 16; o; o >>= 1) sum += __shfl_xor_sync(0xffffffffu, sum, o);
        float inv = 1.f / sum;
        __syncwarp();
        float acc = 0.f;
#pragma unroll 4
        for (int j = 0; j <= jmax; j++) acc += att[warp][j] * Vs[j][lane];
        av[((size_t)i * BB + b) * 64 + h * 32 + lane] = __float2bfloat16(acc * inv);
        __syncwarp();
    }
}

// ---------- mega prep (optional per-k scale on transpose) ----------
__device__ __forceinline__ void tpose_tile(const float* __restrict__ in, bf16* __restrict__ out,
                                           int K, int N, const float* __restrict__ scale)
{
    __shared__ float t[32][33];
    int k0 = blockIdx.y * 32, n0 = blockIdx.x * 32;
    if (k0 >= K || n0 >= N) return;
    int x = threadIdx.x, y = threadIdx.y;
    for (int i = y; i < 32; i += 8)
        t[i][x] = in[(size_t)(k0 + i) * N + n0 + x];
    __syncthreads();
    float s = scale ? scale[k0 + x] : 1.f;
    for (int i = y; i < 32; i += 8)
        out[(size_t)(n0 + i) * K + k0 + x] = __float2bfloat16(s * t[x][i]);
}

__global__ void megaprep_kernel(const float* __restrict__ g1W, const float* __restrict__ g2W,
                                const float* __restrict__ Wq, const float* __restrict__ Wkv,
                                const float* __restrict__ ffW1, const float* __restrict__ Wp,
                                const float* __restrict__ memory,
                                const float* __restrict__ ln1g, const float* __restrict__ ln2g)
{
    int z = blockIdx.z;
    if (z < 12) {
        const float* in = ((z < 6) ? g1W : g2W) + (size_t)(z % 6) * DD * DD;
        bf16* out = ((z < 6) ? gb_g1 : gb_g2) + (size_t)(z % 6) * DD * DD;
        tpose_tile(in, out, DD, DD, 0);
    } else if (z == 12) {
        tpose_tile(Wq, gb_wqkv, DD, 64, ln1g);
    } else if (z == 13) {
        tpose_tile(Wkv, gb_wqkv + 64 * DD, DD, 128, ln1g);
    } else if (z == 14) {
        tpose_tile(Wkv, gb_wkvm, DD, 128, 0);
    } else if (z == 15) {
        tpose_tile(ffW1, gb_ff1, DD, DFF, ln2g);
    } else if (z == 16) {
        int bid = blockIdx.y * 16 + blockIdx.x;
        int tid = threadIdx.y * 32 + threadIdx.x;
        const int n4 = MROW * DD / 4;
        for (int i = bid * 256 + tid; i < n4; i += 256 * 256) {
            float4 v = reinterpret_cast<const float4*>(memory)[i];
            __nv_bfloat162* o = reinterpret_cast<__nv_bfloat162*>(gb_mem + (size_t)i * 4);
            o[0] = __floats2bfloat162_rn(v.x, v.y);
            o[1] = __floats2bfloat162_rn(v.z, v.w);
        }
    } else {
        int jj = blockIdx.y * 16 + blockIdx.x;
        if (jj >= JJ) return;
        __shared__ float pe[DD];
        int tid = threadIdx.y * 32 + threadIdx.x;
        float pos = (float)(JJ - 1 - jj);
        for (int d = tid; d < DD; d += 256) {
            int i = (d < 256) ? d : d - 256;
            float f = __expf(-(float)(2 * i) * (1.f / 512.f) * 9.210340371976184f);
            float a = pos * f;
            pe[d] = (d < 256) ? sinf(a) : cosf(a);
        }
        __syncthreads();
        if (tid < 64) {
            float acc = 0.f;
            for (int d = 0; d < DD; d++) acc += pe[d] * Wp[d * 64 + tid];
            g_p[jj * 64 + tid] = acc;
        }
    }
}

// ---------- LN-fold column constants (parallelized over d-slices) ----------
__global__ void cgb_kernel(const float* __restrict__ Wq, const float* __restrict__ Wkv,
                           const float* __restrict__ ffW1,
                           const float* __restrict__ g1, const float* __restrict__ b1,
                           const float* __restrict__ g2, const float* __restrict__ b2,
                           const float* __restrict__ ffb1,
                           float* __restrict__ cg, float* __restrict__ cbb)
{
    __shared__ float sgs[8][64];
    __shared__ float sbs[8][64];
    int blk = blockIdx.x;      // 0: Wq; 1,2: Wkv halves; 3: ffW1
    int t = threadIdx.x;       // 0..63
    int dy = threadIdx.y;      // 0..7
    float sg = 0.f, sb = 0.f;
    if (blk == 0) {
        for (int i = 0; i < 64; i++) {
            int d = dy * 64 + i;
            float w = Wq[(size_t)d * 64 + t];
            sg += g1[d] * w; sb += b1[d] * w;
        }
    } else if (blk <= 2) {
        int c = (blk - 1) * 64 + t;
        for (int i = 0; i < 64; i++) {
            int d = dy * 64 + i;
            float w = Wkv[(size_t)d * 128 + c];
            sg += g1[d] * w; sb += b1[d] * w;
        }
    } else {
        for (int i = 0; i < 64; i++) {
            int d = dy * 64 + i;
            float w = ffW1[(size_t)d * DFF + t];
            sg += g2[d] * w; sb += b2[d] * w;
        }
    }
    sgs[dy][t] = sg;
    sbs[dy][t] = sb;
    __syncthreads();
    if (dy == 0) {
#pragma unroll
        for (int k = 1; k < 8; k++) { sg += sgs[k][t]; sb += sbs[k][t]; }
        if (blk == 0)      { cg[t] = sg;                 cbb[t] = sb; }
        else if (blk <= 2) { int c = (blk - 1) * 64 + t; cg[64 + c] = sg; cbb[64 + c] = sb; }
        else               { cg[192 + t] = sg;           cbb[192 + t] = sb + ffb1[t]; }
    }
}

// ---------- folded-weight precompute ----------
__global__ void pregemm_kernel(const float* __restrict__ Wout, const float* __restrict__ ffW2,
                               const float* __restrict__ g1W, const float* __restrict__ g2W)
{
    __shared__ float sG[64][33];
    const int slot[3] = {0, 2, 4};
    int m = blockIdx.z;
    const float* A = (m < 3) ? Wout : ffW2;
    const float* G = ((m < 3) ? g1W : g2W) + (size_t)slot[m % 3] * DD * DD;
    bf16* out = gb_cw + (size_t)m * DD * 64;
    int n0 = blockIdx.x * 32, k0 = blockIdx.y * 8;
    int tx = threadIdx.x, ty = threadIdx.y;
    int tid = ty * 32 + tx;
    float acc = 0.f;
    for (int dc = 0; dc < 8; dc++) {
        __syncthreads();
        for (int idx = tid; idx < 64 * 32; idx += 256) {
            int i = idx >> 5, j = idx & 31;
            sG[i][j] = G[(size_t)(dc * 64 + i) * DD + n0 + j];
        }
        __syncthreads();
        const float* Ar = A + (size_t)(k0 + ty) * DD + dc * 64;
#pragma unroll 16
        for (int i = 0; i < 64; i++) acc += Ar[i] * sG[i][tx];
    }
    out[(size_t)(n0 + tx) * 64 + (k0 + ty)] = __float2bfloat16(acc);
}

// ---------- gate-2 combined bias (parallelized over d-slices) ----------
__global__ void bc2_kernel(const float* __restrict__ ffb2, const float* __restrict__ g2W,
                           const float* __restrict__ g2b, float* __restrict__ bc)
{
    __shared__ float sh[8][128];
    const int slot[3] = {0, 2, 4};
    int m = blockIdx.z;
    int n = blockIdx.x * 128 + threadIdx.x;
    int dy = threadIdx.y;
    const float* G = g2W + (size_t)slot[m] * DD * DD;
    float acc = 0.f;
    for (int i = 0; i < 64; i++) {
        int d = dy * 64 + i;
        acc += ffb2[d] * G[(size_t)d * DD + n];
    }
    sh[dy][threadIdx.x] = acc;
    __syncthreads();
    if (dy == 0) {
        float s = g2b[(2 * m) * DD + n] + g2b[(2 * m + 1) * DD + n];
#pragma unroll
        for (int k = 0; k < 8; k++) s += sh[k][threadIdx.x];
        bc[m * DD + n] = s;
    }
}

// ---------- mean pool from bf16 ----------
__global__ void meanpool_bf_kernel(const bf16* __restrict__ in, float* __restrict__ ts)
{
    int idx = blockIdx.x * blockDim.x + threadIdx.x;
    const int n2 = BB * DD / 2;
    if (idx >= n2) return;
    float s0 = 0.f, s1 = 0.f;
    for (int t = 0; t < TT; t++) {
        __nv_bfloat162 v = *reinterpret_cast<const __nv_bfloat162*>(in + (size_t)t * BB * DD + idx * 2);
        s0 += __bfloat162float(v.x);
        s1 += __bfloat162float(v.y);
    }
    const float inv = 1.f / TT;
    *reinterpret_cast<float2*>(ts + (size_t)idx * 2) = make_float2(s0 * inv, s1 * inv);
}

// ---------- final head ----------
__global__ void final_kernel(const float* __restrict__ h3, const float* __restrict__ w,
                             const float* __restrict__ bb, float* __restrict__ out)
{
    int row = blockIdx.x * 4 + (threadIdx.x >> 5);
    int lane = threadIdx.x & 31;
    if (row >= BB) return;
    float s = 0.f;
    for (int k = lane; k < 300; k += 32) s += h3[(size_t)row * 300 + k] * w[k];
#pragma unroll
    for (int o = 16; o; o >>= 1) s += __shfl_xor_sync(0xffffffffu, s, o);
    if (lane == 0) out[row] = fmaxf(s + bb[0], 0.f);
}

// ---------- host ----------
static inline void launch_tc(const bf16* A0, const bf16* W0, int K0,
                             const bf16* A1, const bf16* W1, int K1,
                             int M, int N, int NT,
                             float* Cf, bf16* Cb,
                             const float* b1, const float* b2, float cadd,
                             const bf16* zpre, const bf16* aux, int mode,
                             const float2* rstat = 0)
{
    dim3 grid(N / NT, M / 128);
    if (NT == 128) {
        size_t dsz = 3 * (size_t)(128 + 128) * 144;
        bgemm<128><<<grid, 256, dsz>>>(A0, W0, K0, A1, W1, K1, N, Cf, Cb, b1, b2, cadd, zpre, aux, rstat, mode);
    } else {
        size_t dsz = 3 * (size_t)(128 + 64) * 144;
        bgemm<64><<<grid, 256, dsz>>>(A0, W0, K0, A1, W1, K1, N, Cf, Cb, b1, b2, cadd, zpre, aux, rstat, mode);
    }
}
static inline void launch_sgemm(const float* A, const float* W, float* C,
                                int M, int N, int K, const float* bias, float cadd, int flags)
{
    dim3 grid((N + 63) / 64, (M + 63) / 64);
    sgemm64_kernel<<<grid, 256>>>(A, W, C, M, N, K, bias, cadd, flags);
}

extern "C" void kernel_launch(void* const* d_in, const int* in_sizes, int n_in,
                              void* d_out, int out_size)
{
    const float* x      = (const float*)d_in[0];
    const float* action = (const float*)d_in[1];
    const float* memory = (const float*)d_in[2];
    const float* W_q    = (const float*)d_in[3];
    const float* W_kv   = (const float*)d_in[4];
    const float* W_p    = (const float*)d_in[5];
    const float* W_out  = (const float*)d_in[6];
    const float* u      = (const float*)d_in[7];
    const float* v      = (const float*)d_in[8];
    const float* ln1_g  = (const float*)d_in[9];
    const float* ln1_b  = (const float*)d_in[10];
    const float* ln2_g  = (const float*)d_in[11];
    const float* ln2_b  = (const float*)d_in[12];
    const float* ff_W1  = (const float*)d_in[13];
    const float* ff_b1  = (const float*)d_in[14];
    const float* ff_W2  = (const float*)d_in[15];
    const float* ff_b2  = (const float*)d_in[16];
    const float* g1W    = (const float*)d_in[17];
    const float* g1b    = (const float*)d_in[18];
    const float* g2W    = (const float*)d_in[19];
    const float* g2b    = (const float*)d_in[20];
    const float* d1W    = (const float*)d_in[21];
    const float* d1b    = (const float*)d_in[22];
    const float* d2W    = (const float*)d_in[23];
    const float* d2b    = (const float*)d_in[24];
    const float* d3W    = (const float*)d_in[25];
    const float* d3b    = (const float*)d_in[26];
    const float* d4W    = (const float*)d_in[27];
    const float* d4b    = (const float*)d_in[28];

    cudaFuncSetAttribute(bgemm<128>, cudaFuncAttributeMaxDynamicSharedMemorySize, 111000);
    cudaFuncSetAttribute(bgemm<64>,  cudaFuncAttributeMaxDynamicSharedMemorySize, 84000);

    float *QKV, *KVM, *P, *TS, *H1, *H2, *H3, *BC2, *CG, *CBB;
    float2 *ST1, *ST2;
    bf16 *XB, *MEMB, *RXB, *ZB, *SRCB, *FFHB, *AVB;
    bf16 *WQKVT, *WKVMT, *G1T, *G2T, *FF1G, *CW;
    cudaGetSymbolAddress((void**)&QKV,  g_qkv);
    cudaGetSymbolAddress((void**)&KVM,  g_kvm);
    cudaGetSymbolAddress((void**)&P,    g_p);
    cudaGetSymbolAddress((void**)&TS,   g_ts);
    cudaGetSymbolAddress((void**)&H1,   g_h1);
    cudaGetSymbolAddress((void**)&H2,   g_h2);
    cudaGetSymbolAddress((void**)&H3,   g_h3);
    cudaGetSymbolAddress((void**)&BC2,  g_bc2);
    cudaGetSymbolAddress((void**)&CG,   g_cg);
    cudaGetSymbolAddress((void**)&CBB,  g_cbb);
    cudaGetSymbolAddress((void**)&ST1,  g_st1);
    cudaGetSymbolAddress((void**)&ST2,  g_st2);
    cudaGetSymbolAddress((void**)&XB,   gb_x);
    cudaGetSymbolAddress((void**)&MEMB, gb_mem);
    cudaGetSymbolAddress((void**)&RXB,  gb_rx);
    cudaGetSymbolAddress((void**)&ZB,   gb_z);
    cudaGetSymbolAddress((void**)&SRCB, gb_src);
    cudaGetSymbolAddress((void**)&FFHB, gb_ffh);
    cudaGetSymbolAddress((void**)&AVB,  gb_av);
    cudaGetSymbolAddress((void**)&WQKVT,gb_wqkv);
    cudaGetSymbolAddress((void**)&WKVMT,gb_wkvm);
    cudaGetSymbolAddress((void**)&G1T,  gb_g1);
    cudaGetSymbolAddress((void**)&G2T,  gb_g2);
    cudaGetSymbolAddress((void**)&FF1G, gb_ff1);
    cudaGetSymbolAddress((void**)&CW,   gb_cw);

    const size_t SZ = (size_t)DD * DD;
    const size_t CWS = (size_t)DD * 64;

    // prep
    megaprep_kernel<<<dim3(16, 16, 18), dim3(32, 8)>>>(
        g1W, g2W, W_q, W_kv, ff_W1, W_p, memory, ln1_g, ln2_g);
    pregemm_kernel<<<dim3(16, 8, 6), dim3(32, 8)>>>(W_out, ff_W2, g1W, g2W);
    bc2_kernel<<<dim3(4, 1, 3), dim3(128, 8)>>>(ff_b2, g2W, g2b, BC2);
    cgb_kernel<<<4, dim3(64, 8)>>>(W_q, W_kv, ff_W1, ln1_g, ln1_b, ln2_g, ln2_b, ff_b1, CG, CBB);

    // x stats + bf16 copy
    statx_kernel<<<NROW / 8, 256>>>(x, XB, ST1, NROW);

    // qkv (LN1 folded): src rows only, mode 6
    launch_tc(XB, WQKVT, DD, 0, 0, 0, NROW, 192, 64, QKV, 0, CG, CBB, 0.f, 0, 0, 6, ST1);

    // memory kv (raw weights)
    launch_tc(MEMB, WKVMT, DD, 0, 0, 0, MROW, 128, 128, KVM, 0, 0, 0, 0.f, 0, 0, 0);

    // attention -> AVB (bf16)
    attn_kernel<<<dim3(BB, HH), 128>>>(QKV, KVM, P, u, v, AVB);

    // gate 1 (y-side folded through W_out; K = 64 + 512)
    launch_tc(AVB, CW + 0 * CWS, 64, XB, G1T + 1 * SZ, DD, NROW, DD, 128,
              0, RXB, g1b + 0 * DD, g1b + 1 * DD, 0.f, 0, XB, 4);
    launch_tc(AVB, CW + 1 * CWS, 64, XB, G1T + 3 * SZ, DD, NROW, DD, 128,
              0, ZB, g1b + 2 * DD, g1b + 3 * DD, -BG, 0, 0, 2);
    launch_tc(AVB, CW + 2 * CWS, 64, RXB, G1T + 5 * SZ, DD, NROW, DD, 128,
              0, SRCB, g1b + 4 * DD, g1b + 5 * DD, 0.f, ZB, XB, 5);

    // src stats, then ffh (LN2 folded, relu, bf16)
    statb_kernel<<<NROW / 8, 256>>>(SRCB, ST2, NROW);
    launch_tc(SRCB, FF1G, DD, 0, 0, 0, NROW, DFF, 64, 0, FFHB, CG + 192, CBB + 192, 0.f, 0, 0, 7, ST2);

    // gate 2 (y-side = ff folded through ff_W2)
    launch_tc(FFHB, CW + 3 * CWS, 64, SRCB, G2T + 1 * SZ, DD, NROW, DD, 128,
              0, RXB, BC2 + 0 * DD, 0, 0.f, 0, SRCB, 4);
    launch_tc(FFHB, CW + 4 * CWS, 64, SRCB, G2T + 3 * SZ, DD, NROW, DD, 128,
              0, ZB, BC2 + 1 * DD, 0, -BG, 0, 0, 2);
    launch_tc(FFHB, CW + 5 * CWS, 64, RXB, G2T + 5 * SZ, DD, NROW, DD, 128,
              0, XB, BC2 + 2 * DD, 0, 0.f, ZB, SRCB, 5);

    // mean pool (bf16 in, f32 out)
    meanpool_bf_kernel<<<(BB * DD / 2 + 255) / 256, 256>>>(XB, TS);

    // critic head (exact fp32)
    launch_sgemm(TS, d1W, H1, BB, 1024, DD, d1b, 0.f, 2);
    launch_sgemm(H1, d2W, H2, BB, 512, 1024, nullptr, 0.f, 0);
    launch_sgemm(action, d2W + (size_t)1024 * 512, H2, BB, 512, ACT, d2b, 0.f, 3);
    launch_sgemm(H2, d3W, H3, BB, 300, DD, d3b, 0.f, 2);
    final_kernel<<<BB / 4, 128>>>(H3, d4W, d4b, (float*)d_out);
}